// round 1
// baseline (speedup 1.0000x reference)
#include <cuda_runtime.h>
#include <math.h>

#define NK 10

// ---------------- scratch (static device globals; no allocation) ----------------
__device__ float  g_Apad[3][256][512];   // planar A, y padded/wrapped: [c][x][y+128]
__device__ float  g_Asum[256][256];
__device__ float  g_K[NK][256][256];     // raw (unnormalized) kernels, [k][dx+128][dy+128]
__device__ double g_part[NK][256];       // per-row kernel sums
__device__ double g_ksum[NK];            // kernel normalization sums
__device__ int    g_rad[NK];             // per-k support radius
__device__ float  g_G[NK][256][256];     // growth(U)*h per k
__device__ float  g_U3[3][256][256];     // channel-group sums
__device__ float  g_mu[256*256*6];       // [x][y][c*2+comp]

__constant__ int c_C0[NK] = {0,0,0,1,1,1,2,2,2,0};

// ---------------- 1. prep: planar padded A, Asum, radii ----------------
__global__ void prep_kernel(const float* __restrict__ A,
                            const float* __restrict__ R,
                            const float* __restrict__ r) {
    int x = blockIdx.x, y = threadIdx.x;
    float a0 = A[(x*256+y)*3+0];
    float a1 = A[(x*256+y)*3+1];
    float a2 = A[(x*256+y)*3+2];
    int j  = y + 128;
    int j2 = (y < 128) ? (y + 384) : (y - 128);
    g_Apad[0][x][j]  = a0; g_Apad[1][x][j]  = a1; g_Apad[2][x][j]  = a2;
    g_Apad[0][x][j2] = a0; g_Apad[1][x][j2] = a1; g_Apad[2][x][j2] = a2;
    g_Asum[x][y] = a0 + a1 + a2;
    if (x == 0 && y < NK) {
        // sig = 0.5*(tanh(-(Dk-1)*5)+1) is exactly 0 (fp32) for Dk >= ~2.58.
        // 2.85 gives safety margin; radius in pixels.
        float rc = 2.85f * (R[0] + 15.0f) * r[y];
        int rad = (int)rc + 1;
        rad = max(1, min(127, rad));
        g_rad[y] = rad;
    }
}

// ---------------- 2. build raw kernels + per-row double sums ----------------
__global__ void kbuild_kernel(const float* __restrict__ R,
                              const float* __restrict__ r,
                              const float* __restrict__ a,
                              const float* __restrict__ b,
                              const float* __restrict__ w) {
    int i = blockIdx.x;   // dx + 128
    int k = blockIdx.y;
    int j = threadIdx.x;  // dy + 128
    float fdx = (float)(i - 128);
    float fdy = (float)(j - 128);
    float D  = sqrtf(fdx*fdx + fdy*fdy);
    float Dk = D / ((R[0] + 15.0f) * r[k]);
    float ker = 0.0f;
    #pragma unroll
    for (int t = 0; t < 3; t++) {
        float d = Dk - a[k*3+t];
        ker += b[k*3+t] * expf(-d*d / w[k*3+t]);
    }
    float sig = 0.5f * (tanhf(-(Dk - 1.0f) * 5.0f) + 1.0f);
    float val = sig * ker;
    g_K[k][i][j] = val;

    __shared__ double sd[256];
    sd[j] = (double)val;
    __syncthreads();
    for (int s = 128; s > 0; s >>= 1) {
        if (j < s) sd[j] += sd[j + s];
        __syncthreads();
    }
    if (j == 0) g_part[k][i] = sd[0];
}

// ---------------- 3. reduce row sums -> ksum (deterministic) ----------------
__global__ void ksum_kernel() {
    int k = blockIdx.x, j = threadIdx.x;
    __shared__ double sd[256];
    sd[j] = g_part[k][j];
    __syncthreads();
    for (int s = 128; s > 0; s >>= 1) {
        if (j < s) sd[j] += sd[j + s];
        __syncthreads();
    }
    if (j == 0) g_ksum[k] = sd[0];
}

// ---------------- 4. direct circular conv + growth ----------------
__global__ void conv_kernel(const float* __restrict__ m,
                            const float* __restrict__ s,
                            const float* __restrict__ h) {
    int k = blockIdx.x;       // fastest-varying -> good k mixing across SMs
    int x = blockIdx.y;
    int y = threadIdx.x;
    int c = c_C0[k];
    int rad = g_rad[k];

    const float* __restrict__ Kk = &g_K[k][0][0];
    const float* __restrict__ Ap = &g_Apad[c][0][0];

    double acc = 0.0;
    for (int dx = -rad; dx <= rad; ++dx) {
        int xr = (x - dx) & 255;
        const float* __restrict__ Arow = Ap + xr*512 + (y + 128);
        const float* __restrict__ Krow = Kk + (dx + 128)*256 + 128;
        int rr = rad*rad - dx*dx;
        int radY = min(127, __float2int_rz(sqrtf((float)rr)) + 1);
        float racc = 0.0f;
        #pragma unroll 8
        for (int t = -radY; t <= radY; ++t) {
            racc = fmaf(Krow[t], Arow[-t], racc);
        }
        acc += (double)racc;
    }
    float U  = (float)(acc / g_ksum[k]);
    float gg = (U - m[k]) / s[k];
    float gr = expf(-0.5f * gg * gg) * 2.0f - 1.0f;
    g_G[k][x][y] = gr * h[k];
}

// ---------------- 5. channel-group sums ----------------
__global__ void u3_kernel() {
    int x = blockIdx.x, y = threadIdx.x;
    g_U3[0][x][y] = g_G[0][x][y] + g_G[1][x][y] + g_G[2][x][y] + g_G[9][x][y];
    g_U3[1][x][y] = g_G[3][x][y] + g_G[4][x][y] + g_G[5][x][y];
    g_U3[2][x][y] = g_G[6][x][y] + g_G[7][x][y] + g_G[8][x][y];
}

// ---------------- 6. sobel + flow F + mu ----------------
__device__ __forceinline__ float padv(const float* p, int xx, int yy) {
    return (xx >= 0 && xx < 256 && yy >= 0 && yy < 256) ? p[xx*256 + yy] : 0.0f;
}

__global__ void sobelmu_kernel(const float* __restrict__ A) {
    int x = blockIdx.x, y = threadIdx.x;
    const float* As = &g_Asum[0][0];
    // comp0 = conv with KY = [[-1,-2,-1],[0,0,0],[1,2,1]]
    float nA0 = (padv(As,x-1,y-1) + 2.0f*padv(As,x-1,y) + padv(As,x-1,y+1))
              - (padv(As,x+1,y-1) + 2.0f*padv(As,x+1,y) + padv(As,x+1,y+1));
    // comp1 = conv with KX = [[-1,0,1],[-2,0,2],[-1,0,1]]
    float nA1 = (padv(As,x-1,y-1) + 2.0f*padv(As,x,y-1) + padv(As,x+1,y-1))
              - (padv(As,x-1,y+1) + 2.0f*padv(As,x,y+1) + padv(As,x+1,y+1));

    float px = (float)x + 0.5f;
    float py = (float)y + 0.5f;
    #pragma unroll
    for (int c = 0; c < 3; c++) {
        const float* Uc = &g_U3[c][0][0];
        float nU0 = (padv(Uc,x-1,y-1) + 2.0f*padv(Uc,x-1,y) + padv(Uc,x-1,y+1))
                  - (padv(Uc,x+1,y-1) + 2.0f*padv(Uc,x+1,y) + padv(Uc,x+1,y+1));
        float nU1 = (padv(Uc,x-1,y-1) + 2.0f*padv(Uc,x,y-1) + padv(Uc,x+1,y-1))
                  - (padv(Uc,x-1,y+1) + 2.0f*padv(Uc,x,y+1) + padv(Uc,x+1,y+1));
        float Ac = A[(x*256+y)*3 + c];
        float al = Ac * (1.0f/3.0f);
        al = al * al;
        al = fminf(al, 1.0f);
        float F0 = nU0 * (1.0f - al) - nA0 * al;
        float F1 = nU1 * (1.0f - al) - nA1 * al;
        float d0 = fminf(fmaxf(0.2f * F0, -4.35f), 4.35f);
        float d1 = fminf(fmaxf(0.2f * F1, -4.35f), 4.35f);
        float mux = fminf(fmaxf(px + d0, 0.65f), 255.35f);
        float muy = fminf(fmaxf(py + d1, 0.65f), 255.35f);
        g_mu[(x*256+y)*6 + c*2 + 0] = mux;
        g_mu[(x*256+y)*6 + c*2 + 1] = muy;
    }
}

// ---------------- 7. reintegration tracking (gather form) ----------------
__global__ void gather_kernel(float* __restrict__ out) {
    int x = blockIdx.x, y = threadIdx.x;
    float px = (float)x + 0.5f;
    float py = (float)y + 0.5f;
    float acc0 = 0.0f, acc1 = 0.0f, acc2 = 0.0f;
    const float inv = 1.0f / 1.69f;   // 1/(4*sigma^2)

    #pragma unroll
    for (int dx = -5; dx <= 5; ++dx) {
        int i = (x - dx) & 255;
        #pragma unroll
        for (int dy = -5; dy <= 5; ++dy) {
            int j = (y - dy) & 255;
            const float* mu = g_mu + (i*256 + j)*6;
            #pragma unroll
            for (int c = 0; c < 3; c++) {
                float ax = 1.15f - fabsf(px - mu[2*c + 0]);   // 0.5 + sigma - |dp|
                float ay = 1.15f - fabsf(py - mu[2*c + 1]);
                ax = fminf(fmaxf(ax, 0.0f), 1.0f);
                ay = fminf(fmaxf(ay, 0.0f), 1.0f);
                float area = ax * ay * inv;
                float av = g_Apad[c][i][j + 128];
                if (c == 0) acc0 = fmaf(av, area, acc0);
                else if (c == 1) acc1 = fmaf(av, area, acc1);
                else acc2 = fmaf(av, area, acc2);
            }
        }
    }
    out[(x*256+y)*3 + 0] = acc0;
    out[(x*256+y)*3 + 1] = acc1;
    out[(x*256+y)*3 + 2] = acc2;
}

// ---------------- launch ----------------
extern "C" void kernel_launch(void* const* d_in, const int* in_sizes, int n_in,
                              void* d_out, int out_size) {
    const float* A = (const float*)d_in[0];
    const float* R = (const float*)d_in[1];
    const float* r = (const float*)d_in[2];
    const float* m = (const float*)d_in[3];
    const float* s = (const float*)d_in[4];
    const float* h = (const float*)d_in[5];
    const float* a = (const float*)d_in[6];
    const float* b = (const float*)d_in[7];
    const float* w = (const float*)d_in[8];
    float* out = (float*)d_out;

    prep_kernel<<<256, 256>>>(A, R, r);
    kbuild_kernel<<<dim3(256, NK), 256>>>(R, r, a, b, w);
    ksum_kernel<<<NK, 256>>>();
    conv_kernel<<<dim3(NK, 256), 256>>>(m, s, h);
    u3_kernel<<<256, 256>>>();
    sobelmu_kernel<<<256, 256>>>(A);
    gather_kernel<<<256, 256>>>(out);
}

// round 2
// speedup vs baseline: 4.2533x; 4.2533x over previous
#include <cuda_runtime.h>
#include <math.h>

#define NK 10
#define APW 544   // padded A row width (y+128 valid for y in [-128, 415])

// ---------------- scratch (static device globals; no allocation) ----------------
__device__ __align__(16) float  g_Apad[3][256][APW]; // planar A, y wrapped: [c][x][y+128]
__device__ __align__(16) float  g_Asum[256][256];
__device__ __align__(16) float  g_K[NK][256][256];   // raw kernels, [k][dx+128][dy+128]
__device__ double g_part[NK][256];
__device__ double g_ksum[NK];
__device__ int    g_rad[NK];
__device__ __align__(16) float  g_G[NK][256][256];   // growth(U)*h per k
__device__ __align__(16) float  g_U3[3][256][256];
__device__ __align__(16) float  g_mu[256*256*6];

__constant__ int c_C0[NK] = {0,0,0,1,1,1,2,2,2,0};

// ---------------- 1. prep: planar padded A, Asum, radii ----------------
__global__ void prep_kernel(const float* __restrict__ A,
                            const float* __restrict__ R,
                            const float* __restrict__ r) {
    int x = blockIdx.x, y = threadIdx.x;
    float a0 = A[(x*256+y)*3+0];
    float a1 = A[(x*256+y)*3+1];
    float a2 = A[(x*256+y)*3+2];
    g_Asum[x][y] = a0 + a1 + a2;
    // fill padded rows: position j holds A[(j-128) mod 256]
    for (int j = y; j < APW; j += 256) {
        int src = (j - 128) & 255;
        float v0 = A[(x*256+src)*3+0];
        float v1 = A[(x*256+src)*3+1];
        float v2 = A[(x*256+src)*3+2];
        g_Apad[0][x][j] = v0;
        g_Apad[1][x][j] = v1;
        g_Apad[2][x][j] = v2;
    }
    if (x == 0 && y < NK) {
        // sig = 0.5*(tanh(-(Dk-1)*5)+1) underflows to exactly 0 past Dk~2.8.
        float rc = 2.85f * (R[0] + 15.0f) * r[y];
        int rad = (int)rc + 1;
        rad = max(1, min(127, rad));
        g_rad[y] = rad;
    }
}

// ---------------- 2. build raw kernels + per-row double sums ----------------
__global__ void kbuild_kernel(const float* __restrict__ R,
                              const float* __restrict__ r,
                              const float* __restrict__ a,
                              const float* __restrict__ b,
                              const float* __restrict__ w) {
    int i = blockIdx.x;   // dx + 128
    int k = blockIdx.y;
    int j = threadIdx.x;  // dy + 128
    float fdx = (float)(i - 128);
    float fdy = (float)(j - 128);
    float D  = sqrtf(fdx*fdx + fdy*fdy);
    float Dk = D / ((R[0] + 15.0f) * r[k]);
    float ker = 0.0f;
    #pragma unroll
    for (int t = 0; t < 3; t++) {
        float d = Dk - a[k*3+t];
        ker += b[k*3+t] * expf(-d*d / w[k*3+t]);
    }
    float sig = 0.5f * (tanhf(-(Dk - 1.0f) * 5.0f) + 1.0f);
    float val = sig * ker;
    g_K[k][i][j] = val;

    __shared__ double sd[256];
    sd[j] = (double)val;
    __syncthreads();
    for (int s = 128; s > 0; s >>= 1) {
        if (j < s) sd[j] += sd[j + s];
        __syncthreads();
    }
    if (j == 0) g_part[k][i] = sd[0];
}

// ---------------- 3. reduce row sums -> ksum (deterministic) ----------------
__global__ void ksum_kernel() {
    int k = blockIdx.x, j = threadIdx.x;
    __shared__ double sd[256];
    sd[j] = g_part[k][j];
    __syncthreads();
    for (int s = 128; s > 0; s >>= 1) {
        if (j < s) sd[j] += sd[j + s];
        __syncthreads();
    }
    if (j == 0) g_ksum[k] = sd[0];
}

// ---------------- 4. direct circular conv + growth ----------------
// Uses K's dy-symmetry: out[y] = sum_dx sum_u K[dx][u] * A[x-dx][y+u].
// Each thread computes 4 consecutive y outputs via float4 sliding window.
__global__ void __launch_bounds__(128) conv_kernel(const float* __restrict__ m,
                                                   const float* __restrict__ s,
                                                   const float* __restrict__ h) {
    int k = blockIdx.x;
    int x = blockIdx.y * 2 + threadIdx.y;     // one x-row per 64-thread group
    int c = c_C0[k];
    int rad = g_rad[k];
    int y0 = threadIdx.x << 2;                // 4 outputs: y0..y0+3

    const float* __restrict__ Kbase = &g_K[k][0][0];
    const float* __restrict__ Ap = &g_Apad[c][0][0];
    int yb = 128 + y0;

    double acc0 = 0.0, acc1 = 0.0, acc2 = 0.0, acc3 = 0.0;

    for (int dx = -rad; dx <= rad; ++dx) {
        const float* __restrict__ Arow = Ap + ((x - dx) & 255) * APW + yb;
        const float* __restrict__ Krow = Kbase + (dx + 128) * 256 + 128;
        int rr = rad*rad - dx*dx;
        int radY = min(127, __float2int_rz(sqrtf((float)rr)) + 1);
        int us = -((radY + 3) & ~3);          // aligned start, covers [-radY, radY]

        float r0 = 0.f, r1 = 0.f, r2 = 0.f, r3 = 0.f;
        float4 ap = *(const float4*)(Arow + us);
        #pragma unroll 2
        for (int u = us; u <= radY; u += 4) {
            float4 an = *(const float4*)(Arow + u + 4);
            float4 kv = *(const float4*)(Krow + u);
            r0 = fmaf(kv.x, ap.x, r0); r1 = fmaf(kv.x, ap.y, r1);
            r2 = fmaf(kv.x, ap.z, r2); r3 = fmaf(kv.x, ap.w, r3);
            r0 = fmaf(kv.y, ap.y, r0); r1 = fmaf(kv.y, ap.z, r1);
            r2 = fmaf(kv.y, ap.w, r2); r3 = fmaf(kv.y, an.x, r3);
            r0 = fmaf(kv.z, ap.z, r0); r1 = fmaf(kv.z, ap.w, r1);
            r2 = fmaf(kv.z, an.x, r2); r3 = fmaf(kv.z, an.y, r3);
            r0 = fmaf(kv.w, ap.w, r0); r1 = fmaf(kv.w, an.x, r1);
            r2 = fmaf(kv.w, an.y, r2); r3 = fmaf(kv.w, an.z, r3);
            ap = an;
        }
        acc0 += (double)r0; acc1 += (double)r1;
        acc2 += (double)r2; acc3 += (double)r3;
    }

    double inv_ksum = 1.0 / g_ksum[k];
    float mk = m[k], sk = s[k], hk = h[k];
    float* __restrict__ Gout = &g_G[k][x][y0];
    double accs[4] = {acc0, acc1, acc2, acc3};
    #pragma unroll
    for (int q = 0; q < 4; q++) {
        float U  = (float)(accs[q] * inv_ksum);
        float gg = (U - mk) / sk;
        float gr = expf(-0.5f * gg * gg) * 2.0f - 1.0f;
        Gout[q] = gr * hk;
    }
}

// ---------------- 5. channel-group sums ----------------
__global__ void u3_kernel() {
    int x = blockIdx.x, y = threadIdx.x;
    g_U3[0][x][y] = g_G[0][x][y] + g_G[1][x][y] + g_G[2][x][y] + g_G[9][x][y];
    g_U3[1][x][y] = g_G[3][x][y] + g_G[4][x][y] + g_G[5][x][y];
    g_U3[2][x][y] = g_G[6][x][y] + g_G[7][x][y] + g_G[8][x][y];
}

// ---------------- 6. sobel + flow F + mu ----------------
__device__ __forceinline__ float padv(const float* p, int xx, int yy) {
    return (xx >= 0 && xx < 256 && yy >= 0 && yy < 256) ? p[xx*256 + yy] : 0.0f;
}

__global__ void sobelmu_kernel(const float* __restrict__ A) {
    int x = blockIdx.x, y = threadIdx.x;
    const float* As = &g_Asum[0][0];
    float nA0 = (padv(As,x-1,y-1) + 2.0f*padv(As,x-1,y) + padv(As,x-1,y+1))
              - (padv(As,x+1,y-1) + 2.0f*padv(As,x+1,y) + padv(As,x+1,y+1));
    float nA1 = (padv(As,x-1,y-1) + 2.0f*padv(As,x,y-1) + padv(As,x+1,y-1))
              - (padv(As,x-1,y+1) + 2.0f*padv(As,x,y+1) + padv(As,x+1,y+1));

    float px = (float)x + 0.5f;
    float py = (float)y + 0.5f;
    #pragma unroll
    for (int c = 0; c < 3; c++) {
        const float* Uc = &g_U3[c][0][0];
        float nU0 = (padv(Uc,x-1,y-1) + 2.0f*padv(Uc,x-1,y) + padv(Uc,x-1,y+1))
                  - (padv(Uc,x+1,y-1) + 2.0f*padv(Uc,x+1,y) + padv(Uc,x+1,y+1));
        float nU1 = (padv(Uc,x-1,y-1) + 2.0f*padv(Uc,x,y-1) + padv(Uc,x+1,y-1))
                  - (padv(Uc,x-1,y+1) + 2.0f*padv(Uc,x,y+1) + padv(Uc,x+1,y+1));
        float Ac = A[(x*256+y)*3 + c];
        float al = Ac * (1.0f/3.0f);
        al = al * al;
        al = fminf(al, 1.0f);
        float F0 = nU0 * (1.0f - al) - nA0 * al;
        float F1 = nU1 * (1.0f - al) - nA1 * al;
        float d0 = fminf(fmaxf(0.2f * F0, -4.35f), 4.35f);
        float d1 = fminf(fmaxf(0.2f * F1, -4.35f), 4.35f);
        float mux = fminf(fmaxf(px + d0, 0.65f), 255.35f);
        float muy = fminf(fmaxf(py + d1, 0.65f), 255.35f);
        g_mu[(x*256+y)*6 + c*2 + 0] = mux;
        g_mu[(x*256+y)*6 + c*2 + 1] = muy;
    }
}

// ---------------- 7. reintegration tracking (gather form) ----------------
__global__ void gather_kernel(float* __restrict__ out) {
    int x = blockIdx.x, y = threadIdx.x;
    float px = (float)x + 0.5f;
    float py = (float)y + 0.5f;
    float acc0 = 0.0f, acc1 = 0.0f, acc2 = 0.0f;
    const float inv = 1.0f / 1.69f;   // 1/(4*sigma^2)

    #pragma unroll
    for (int dx = -5; dx <= 5; ++dx) {
        int i = (x - dx) & 255;
        #pragma unroll
        for (int dy = -5; dy <= 5; ++dy) {
            int j = (y - dy) & 255;
            const float* mu = g_mu + (i*256 + j)*6;
            #pragma unroll
            for (int c = 0; c < 3; c++) {
                float ax = 1.15f - fabsf(px - mu[2*c + 0]);
                float ay = 1.15f - fabsf(py - mu[2*c + 1]);
                ax = fminf(fmaxf(ax, 0.0f), 1.0f);
                ay = fminf(fmaxf(ay, 0.0f), 1.0f);
                float area = ax * ay * inv;
                float av = g_Apad[c][i][j + 128];
                if (c == 0) acc0 = fmaf(av, area, acc0);
                else if (c == 1) acc1 = fmaf(av, area, acc1);
                else acc2 = fmaf(av, area, acc2);
            }
        }
    }
    out[(x*256+y)*3 + 0] = acc0;
    out[(x*256+y)*3 + 1] = acc1;
    out[(x*256+y)*3 + 2] = acc2;
}

// ---------------- launch ----------------
extern "C" void kernel_launch(void* const* d_in, const int* in_sizes, int n_in,
                              void* d_out, int out_size) {
    const float* A = (const float*)d_in[0];
    const float* R = (const float*)d_in[1];
    const float* r = (const float*)d_in[2];
    const float* m = (const float*)d_in[3];
    const float* s = (const float*)d_in[4];
    const float* h = (const float*)d_in[5];
    const float* a = (const float*)d_in[6];
    const float* b = (const float*)d_in[7];
    const float* w = (const float*)d_in[8];
    float* out = (float*)d_out;

    prep_kernel<<<256, 256>>>(A, R, r);
    kbuild_kernel<<<dim3(256, NK), 256>>>(R, r, a, b, w);
    ksum_kernel<<<NK, 256>>>();
    conv_kernel<<<dim3(NK, 128), dim3(64, 2)>>>(m, s, h);
    u3_kernel<<<256, 256>>>();
    sobelmu_kernel<<<256, 256>>>(A);
    gather_kernel<<<256, 256>>>(out);
}

// round 3
// speedup vs baseline: 5.1653x; 1.2144x over previous
#include <cuda_runtime.h>
#include <math.h>

#define NK 10
#define APW 544     // padded A row width (y+128 valid for y in [-128, 415])
#define CHUNK 32    // dx rows per partial-conv block
#define MAXCH 8     // ceil(255/32)

// ---------------- scratch (static device globals; no allocation) ----------------
__device__ __align__(16) float  g_Apad[3][256][APW]; // planar A, y wrapped: [c][x][y+128]
__device__ __align__(16) float  g_Asum[256][256];
__device__ __align__(16) float  g_K[NK][256][256];   // raw kernels, [k][dx+128][dy+128]
__device__ double g_part[NK][256];
__device__ double g_ksum[NK];
__device__ int    g_rad[NK];
__device__ int    g_nch[NK];
__device__ __align__(16) float  g_pc[NK][MAXCH][256][256];  // partial conv sums (20MB)
__device__ __align__(16) float  g_U3[3][256][256];
__device__ __align__(16) float  g_mu[256*256*6];

__constant__ int c_C0[NK]  = {0,0,0,1,1,1,2,2,2,0};
__constant__ int c_grp[NK] = {0,0,0,1,1,1,2,2,2,0};

// ---------------- 1. prep: planar padded A, Asum, radii ----------------
__global__ void prep_kernel(const float* __restrict__ A,
                            const float* __restrict__ R,
                            const float* __restrict__ r) {
    int x = blockIdx.x, y = threadIdx.x;
    float a0 = A[(x*256+y)*3+0];
    float a1 = A[(x*256+y)*3+1];
    float a2 = A[(x*256+y)*3+2];
    g_Asum[x][y] = a0 + a1 + a2;
    for (int j = y; j < APW; j += 256) {
        int src = (j - 128) & 255;
        float v0 = A[(x*256+src)*3+0];
        float v1 = A[(x*256+src)*3+1];
        float v2 = A[(x*256+src)*3+2];
        g_Apad[0][x][j] = v0;
        g_Apad[1][x][j] = v1;
        g_Apad[2][x][j] = v2;
    }
    if (x == 0 && y < NK) {
        // sig = 0.5*(tanh(-(Dk-1)*5)+1) underflows to exactly 0 past Dk~2.8.
        float rc = 2.85f * (R[0] + 15.0f) * r[y];
        int rad = (int)rc + 1;
        rad = max(1, min(127, rad));
        g_rad[y] = rad;
        g_nch[y] = (2*rad + 1 + CHUNK - 1) / CHUNK;
    }
}

// ---------------- 2. build raw kernels + per-row double sums ----------------
__global__ void kbuild_kernel(const float* __restrict__ R,
                              const float* __restrict__ r,
                              const float* __restrict__ a,
                              const float* __restrict__ b,
                              const float* __restrict__ w) {
    int i = blockIdx.x;   // dx + 128
    int k = blockIdx.y;
    int j = threadIdx.x;  // dy + 128
    float fdx = (float)(i - 128);
    float fdy = (float)(j - 128);
    float D  = sqrtf(fdx*fdx + fdy*fdy);
    float Dk = D / ((R[0] + 15.0f) * r[k]);
    float ker = 0.0f;
    #pragma unroll
    for (int t = 0; t < 3; t++) {
        float d = Dk - a[k*3+t];
        ker += b[k*3+t] * expf(-d*d / w[k*3+t]);
    }
    float sig = 0.5f * (tanhf(-(Dk - 1.0f) * 5.0f) + 1.0f);
    float val = sig * ker;
    g_K[k][i][j] = val;

    __shared__ double sd[256];
    sd[j] = (double)val;
    __syncthreads();
    for (int s = 128; s > 0; s >>= 1) {
        if (j < s) sd[j] += sd[j + s];
        __syncthreads();
    }
    if (j == 0) g_part[k][i] = sd[0];
}

// ---------------- 3. reduce row sums -> ksum (deterministic) ----------------
__global__ void ksum_kernel() {
    int k = blockIdx.x, j = threadIdx.x;
    __shared__ double sd[256];
    sd[j] = g_part[k][j];
    __syncthreads();
    for (int s = 128; s > 0; s >>= 1) {
        if (j < s) sd[j] += sd[j + s];
        __syncthreads();
    }
    if (j == 0) g_ksum[k] = sd[0];
}

// ---------------- 4. partial circular conv (dx-chunked for load balance) ----------------
// out[y] = sum_dx sum_u K[dx][u] * A[x-dx][y+u]  (K symmetric in u).
// Each block handles CHUNK dx rows for 2 x rows; threads do 4 y outputs each.
__global__ void __launch_bounds__(128) convp_kernel() {
    int k  = blockIdx.x;
    int ch = blockIdx.y;
    int rad = g_rad[k];
    if (ch >= g_nch[k]) return;

    int x  = blockIdx.z * 2 + threadIdx.y;
    int c  = c_C0[k];
    int y0 = threadIdx.x << 2;
    int yb = 128 + y0;

    int dx0 = -rad + ch * CHUNK;
    int dx1 = min(rad, dx0 + CHUNK - 1);

    const float* __restrict__ Kbase = &g_K[k][0][0];
    const float* __restrict__ Ap = &g_Apad[c][0][0];

    float acc0 = 0.f, acc1 = 0.f, acc2 = 0.f, acc3 = 0.f;

    for (int dx = dx0; dx <= dx1; ++dx) {
        const float* __restrict__ Arow = Ap + ((x - dx) & 255) * APW + yb;
        const float* __restrict__ Krow = Kbase + (dx + 128) * 256 + 128;
        int rr = rad*rad - dx*dx;
        int radY = min(127, __float2int_rz(sqrtf((float)rr)) + 1);
        int us = -((radY + 3) & ~3);          // aligned start, covers [-radY, radY]

        float r0 = 0.f, r1 = 0.f, r2 = 0.f, r3 = 0.f;
        float4 ap = *(const float4*)(Arow + us);
        #pragma unroll 2
        for (int u = us; u <= radY; u += 4) {
            float4 an = *(const float4*)(Arow + u + 4);
            float4 kv = *(const float4*)(Krow + u);
            r0 = fmaf(kv.x, ap.x, r0); r1 = fmaf(kv.x, ap.y, r1);
            r2 = fmaf(kv.x, ap.z, r2); r3 = fmaf(kv.x, ap.w, r3);
            r0 = fmaf(kv.y, ap.y, r0); r1 = fmaf(kv.y, ap.z, r1);
            r2 = fmaf(kv.y, ap.w, r2); r3 = fmaf(kv.y, an.x, r3);
            r0 = fmaf(kv.z, ap.z, r0); r1 = fmaf(kv.z, ap.w, r1);
            r2 = fmaf(kv.z, an.x, r2); r3 = fmaf(kv.z, an.y, r3);
            r0 = fmaf(kv.w, ap.w, r0); r1 = fmaf(kv.w, an.x, r1);
            r2 = fmaf(kv.w, an.y, r2); r3 = fmaf(kv.w, an.z, r3);
            ap = an;
        }
        acc0 += r0; acc1 += r1; acc2 += r2; acc3 += r3;
    }

    float4 outv = make_float4(acc0, acc1, acc2, acc3);
    *(float4*)&g_pc[k][ch][x][y0] = outv;
}

// ---------------- 5. combine partials + growth + channel-group sums ----------------
__global__ void combine_kernel(const float* __restrict__ m,
                               const float* __restrict__ s,
                               const float* __restrict__ h) {
    int x = blockIdx.x, y = threadIdx.x;
    float u0 = 0.f, u1 = 0.f, u2 = 0.f;
    #pragma unroll
    for (int k = 0; k < NK; k++) {
        int nch = g_nch[k];
        double acc = 0.0;
        for (int ch = 0; ch < nch; ch++)
            acc += (double)g_pc[k][ch][x][y];
        float U  = (float)(acc / g_ksum[k]);
        float gg = (U - m[k]) / s[k];
        float gr = (expf(-0.5f * gg * gg) * 2.0f - 1.0f) * h[k];
        int grp = c_grp[k];
        if (grp == 0) u0 += gr;
        else if (grp == 1) u1 += gr;
        else u2 += gr;
    }
    g_U3[0][x][y] = u0;
    g_U3[1][x][y] = u1;
    g_U3[2][x][y] = u2;
}

// ---------------- 6. sobel + flow F + mu ----------------
__device__ __forceinline__ float padv(const float* p, int xx, int yy) {
    return (xx >= 0 && xx < 256 && yy >= 0 && yy < 256) ? p[xx*256 + yy] : 0.0f;
}

__global__ void sobelmu_kernel(const float* __restrict__ A) {
    int x = blockIdx.x, y = threadIdx.x;
    const float* As = &g_Asum[0][0];
    float nA0 = (padv(As,x-1,y-1) + 2.0f*padv(As,x-1,y) + padv(As,x-1,y+1))
              - (padv(As,x+1,y-1) + 2.0f*padv(As,x+1,y) + padv(As,x+1,y+1));
    float nA1 = (padv(As,x-1,y-1) + 2.0f*padv(As,x,y-1) + padv(As,x+1,y-1))
              - (padv(As,x-1,y+1) + 2.0f*padv(As,x,y+1) + padv(As,x+1,y+1));

    float px = (float)x + 0.5f;
    float py = (float)y + 0.5f;
    #pragma unroll
    for (int c = 0; c < 3; c++) {
        const float* Uc = &g_U3[c][0][0];
        float nU0 = (padv(Uc,x-1,y-1) + 2.0f*padv(Uc,x-1,y) + padv(Uc,x-1,y+1))
                  - (padv(Uc,x+1,y-1) + 2.0f*padv(Uc,x+1,y) + padv(Uc,x+1,y+1));
        float nU1 = (padv(Uc,x-1,y-1) + 2.0f*padv(Uc,x,y-1) + padv(Uc,x+1,y-1))
                  - (padv(Uc,x-1,y+1) + 2.0f*padv(Uc,x,y+1) + padv(Uc,x+1,y+1));
        float Ac = A[(x*256+y)*3 + c];
        float al = Ac * (1.0f/3.0f);
        al = al * al;
        al = fminf(al, 1.0f);
        float F0 = nU0 * (1.0f - al) - nA0 * al;
        float F1 = nU1 * (1.0f - al) - nA1 * al;
        float d0 = fminf(fmaxf(0.2f * F0, -4.35f), 4.35f);
        float d1 = fminf(fmaxf(0.2f * F1, -4.35f), 4.35f);
        float mux = fminf(fmaxf(px + d0, 0.65f), 255.35f);
        float muy = fminf(fmaxf(py + d1, 0.65f), 255.35f);
        g_mu[(x*256+y)*6 + c*2 + 0] = mux;
        g_mu[(x*256+y)*6 + c*2 + 1] = muy;
    }
}

// ---------------- 7. reintegration tracking (gather form) ----------------
__global__ void gather_kernel(float* __restrict__ out) {
    int x = blockIdx.x, y = threadIdx.x;
    float px = (float)x + 0.5f;
    float py = (float)y + 0.5f;
    float acc0 = 0.0f, acc1 = 0.0f, acc2 = 0.0f;
    const float inv = 1.0f / 1.69f;   // 1/(4*sigma^2)

    #pragma unroll
    for (int dx = -5; dx <= 5; ++dx) {
        int i = (x - dx) & 255;
        #pragma unroll
        for (int dy = -5; dy <= 5; ++dy) {
            int j = (y - dy) & 255;
            const float* mu = g_mu + (i*256 + j)*6;
            #pragma unroll
            for (int c = 0; c < 3; c++) {
                float ax = 1.15f - fabsf(px - mu[2*c + 0]);
                float ay = 1.15f - fabsf(py - mu[2*c + 1]);
                ax = fminf(fmaxf(ax, 0.0f), 1.0f);
                ay = fminf(fmaxf(ay, 0.0f), 1.0f);
                float area = ax * ay * inv;
                float av = g_Apad[c][i][j + 128];
                if (c == 0) acc0 = fmaf(av, area, acc0);
                else if (c == 1) acc1 = fmaf(av, area, acc1);
                else acc2 = fmaf(av, area, acc2);
            }
        }
    }
    out[(x*256+y)*3 + 0] = acc0;
    out[(x*256+y)*3 + 1] = acc1;
    out[(x*256+y)*3 + 2] = acc2;
}

// ---------------- launch ----------------
extern "C" void kernel_launch(void* const* d_in, const int* in_sizes, int n_in,
                              void* d_out, int out_size) {
    const float* A = (const float*)d_in[0];
    const float* R = (const float*)d_in[1];
    const float* r = (const float*)d_in[2];
    const float* m = (const float*)d_in[3];
    const float* s = (const float*)d_in[4];
    const float* h = (const float*)d_in[5];
    const float* a = (const float*)d_in[6];
    const float* b = (const float*)d_in[7];
    const float* w = (const float*)d_in[8];
    float* out = (float*)d_out;

    prep_kernel<<<256, 256>>>(A, R, r);
    kbuild_kernel<<<dim3(256, NK), 256>>>(R, r, a, b, w);
    ksum_kernel<<<NK, 256>>>();
    convp_kernel<<<dim3(NK, MAXCH, 128), dim3(64, 2)>>>();
    combine_kernel<<<256, 256>>>(m, s, h);
    sobelmu_kernel<<<256, 256>>>(A);
    gather_kernel<<<256, 256>>>(out);
}